// round 3
// baseline (speedup 1.0000x reference)
#include <cuda_runtime.h>
#include <cstdint>

// Problem dims
#define BB 8
#define DD 1024
#define TT 8192
#define NCB 9
#define KK 1024
#define NT (BB*TT)        // 65536 tokens
#define CN (NCB*8)        // 72

// Output layout (float32, tuple flattened in order)
#define OFF_CODES ((size_t)BB*DD*TT)                  // 67108864
#define OFF_LAT   (OFF_CODES + (size_t)BB*NCB*TT)     // 67698688
#define OFF_CL    (OFF_LAT + (size_t)BB*CN*TT)        // 72417280

// Stage kernel dynamic smem: win 8192 + wout 8192 + ob 1024 + cb2 8192 + cc 1024 floats
#define SMEM_ST ((8192 + 8192 + 1024 + 8192 + 1024)*4)   // 106496
#define SMEM_F  ((8192 + 1024)*4)                          // 36864

// Scratch (__device__ globals: allowed; no runtime allocation)
__device__ float g_res[(size_t)BB*DD*TT];   // 268MB residual, in-place updated
__device__ __align__(16) float g_Win[CN*DD];      // [c_global][d]
__device__ __align__(16) float g_Wout[DD*CN];     // [d][c_global]
__device__ __align__(16) float g_cbn[NCB*KK*8];   // normalized codebook (ref fp32 semantics)
__device__ __align__(16) float g_cc[NCB*KK];      // sum(c_n*c_n) per codeword
__device__ __align__(16) float g_zqst[8*NT];      // straight-through values, [c][token]
__device__ __align__(16) float g_lpart[NCB*256];

// ---------------------------------------------------------------------------
// f32x2 packed helpers (each lane an exact IEEE fp32 op)
// ---------------------------------------------------------------------------
__device__ __forceinline__ unsigned long long pk2(float lo, float hi) {
    unsigned long long r;
    asm("mov.b64 %0, {%1, %2};" : "=l"(r) : "f"(lo), "f"(hi));
    return r;
}
__device__ __forceinline__ void upk2(unsigned long long v, float& lo, float& hi) {
    asm("mov.b64 {%0, %1}, %2;" : "=f"(lo), "=f"(hi) : "l"(v));
}
__device__ __forceinline__ unsigned long long ffma2(unsigned long long a, unsigned long long b, unsigned long long c) {
    unsigned long long r;
    asm("fma.rn.f32x2 %0, %1, %2, %3;" : "=l"(r) : "l"(a), "l"(b), "l"(c));
    return r;
}
__device__ __forceinline__ unsigned long long fmul2(unsigned long long a, unsigned long long b) {
    unsigned long long r;
    asm("mul.rn.f32x2 %0, %1, %2;" : "=l"(r) : "l"(a), "l"(b));
    return r;
}
__device__ __forceinline__ unsigned long long fadd2(unsigned long long a, unsigned long long b) {
    unsigned long long r;
    asm("add.rn.f32x2 %0, %1, %2;" : "=l"(r) : "l"(a), "l"(b));
    return r;
}

// ---------------------------------------------------------------------------
// Prep: weight-norm input rows (fp64 norms), layout [c][d]
// ---------------------------------------------------------------------------
__global__ void kp_win(const float* __restrict__ in_v, const float* __restrict__ in_g) {
    const int row = blockIdx.x;               // 0..71
    const float* src = in_v + (size_t)row * DD;
    __shared__ double red[256];
    double ss = 0.0;
    for (int d = threadIdx.x; d < DD; d += 256) { double v = src[d]; ss += v*v; }
    red[threadIdx.x] = ss; __syncthreads();
    for (int s = 128; s > 0; s >>= 1) {
        if (threadIdx.x < s) red[threadIdx.x] += red[threadIdx.x + s];
        __syncthreads();
    }
    const float scale = (float)((double)in_g[row] / sqrt(red[0]));
    for (int d = threadIdx.x; d < DD; d += 256) g_Win[row*DD + d] = src[d] * scale;
}

// ---------------------------------------------------------------------------
// Prep: weight-norm output rows (norm over C=8, fp64), layout [d][c_global]
// ---------------------------------------------------------------------------
__global__ void kp_wout(const float* __restrict__ out_v, const float* __restrict__ out_g) {
    const int i = blockIdx.x * 256 + threadIdx.x;   // (n, d)
    if (i >= NCB*DD) return;
    const int n = i / DD, d = i - n*DD;
    const float* v = out_v + (size_t)i * 8;
    double ss = 0.0;
    #pragma unroll
    for (int c = 0; c < 8; c++) { double x = v[c]; ss += x*x; }
    const float sc = (float)((double)out_g[i] / sqrt(ss));
    #pragma unroll
    for (int c = 0; c < 8; c++) g_Wout[d*CN + n*8 + c] = v[c] * sc;
}

// ---------------------------------------------------------------------------
// Prep: normalized codebook + cc = sum(c_n^2), replicating fp32 elementwise ops
// ---------------------------------------------------------------------------
__global__ void kp_cb(const float* __restrict__ cb) {
    const int r = blockIdx.x * 256 + threadIdx.x;   // (n, k)
    if (r >= NCB*KK) return;
    const float* v = cb + (size_t)r * 8;
    float ss = 0.f;
    #pragma unroll
    for (int c = 0; c < 8; c++) ss = __fadd_rn(ss, __fmul_rn(v[c], v[c]));
    const float nr = fmaxf(__fsqrt_rn(ss), 1e-12f);
    float cn[8];
    #pragma unroll
    for (int c = 0; c < 8; c++) cn[c] = __fdiv_rn(v[c], nr);
    #pragma unroll
    for (int c = 0; c < 8; c++) g_cbn[(size_t)r*8 + c] = cn[c];
    float s2 = 0.f;
    #pragma unroll
    for (int c = 0; c < 8; c++) s2 = __fadd_rn(s2, __fmul_rn(cn[c], cn[c]));
    g_cc[r] = s2;
}

// ---------------------------------------------------------------------------
// Stage kernel N (0..8). Faithfully replicates the reference chain:
//   (N>=1) res <- res - (W_out[N-1] . zqst_{N-1} + ob[N-1])    [fp32, in-place]
//   z_e = W_in[N] . res + ib[N]
//   e_n = e / max(||e||, eps); dist_k = (ee - 2 e.c_k) + cc_k; argmin first-wins
//   q = cb[N][k*]; zqst = z_e + (q - z_e); writes codes/latents/zqst/loss part
// Block: 256 threads, 256 tokens; thread owns one token end-to-end.
// ---------------------------------------------------------------------------
template<int N>
__global__ void __launch_bounds__(256, 2) k_stage(const float* __restrict__ z,
                                                  const float* __restrict__ in_b,
                                                  const float* __restrict__ out_b,
                                                  const float* __restrict__ cb_raw,
                                                  float* __restrict__ out) {
    extern __shared__ float sm[];
    float* win_s  = sm;              // [1024][8]
    float* wout_s = sm + 8192;       // [1024][8]   (stage N-1), N>=1
    float* ob_s   = sm + 16384;      // [1024]
    float* cb2_s  = sm + 17408;      // [512][8c][2k] pair-interleaved (8192 floats)
    float* cc2_s  = cb2_s + 8192;    // [1024] (k-order)
    __shared__ float red[256];

    const int tid = threadIdx.x;
    const int token = blockIdx.x * 256 + tid;
    const int b = token >> 13;
    const int t = token & (TT - 1);

    for (int i = tid; i < 8192; i += 256) {
        const int d = i >> 3, c = i & 7;
        win_s[i] = g_Win[(N*8 + c)*DD + d];
        if (N >= 1) wout_s[i] = g_Wout[d*CN + (N-1)*8 + c];
    }
    if (N >= 1)
        for (int d = tid; d < DD; d += 256) ob_s[d] = out_b[(N-1)*DD + d];
    for (int i = tid; i < KK*8; i += 256) {
        const int k = i >> 3, c = i & 7;
        cb2_s[(k >> 1)*16 + c*2 + (k & 1)] = g_cbn[(size_t)N*KK*8 + i];
    }
    for (int k = tid; k < KK; k += 256) cc2_s[k] = g_cc[N*KK + k];

    float zq[8];
    if (N >= 1) {
        #pragma unroll
        for (int c = 0; c < 8; c++) zq[c] = g_zqst[(size_t)c*NT + token];
    }
    __syncthreads();

    // ---- Phase 1: residual update (in place) + z_e accumulation ----
    const float* rin = (N <= 1) ? z : (const float*)g_res;
    size_t off = (size_t)b*DD*TT + t;
    unsigned long long accp[4] = {0ull, 0ull, 0ull, 0ull};
    #pragma unroll 4
    for (int d = 0; d < DD; d++) {
        float r = __ldg(rin + off);
        if (N >= 1) {
            float dt = 0.f;
            #pragma unroll
            for (int c = 0; c < 8; c++) dt = fmaf(wout_s[d*8 + c], zq[c], dt);
            const float pr = __fadd_rn(dt, ob_s[d]);   // z_q_i = dot + ob
            r = __fsub_rn(r, pr);                      // residual - z_q_i
            g_res[off] = r;
        }
        const unsigned long long rp = pk2(r, r);
        const ulonglong2 w01 = *(const ulonglong2*)&win_s[d*8];
        const ulonglong2 w23 = *(const ulonglong2*)&win_s[d*8 + 4];
        accp[0] = ffma2(w01.x, rp, accp[0]);
        accp[1] = ffma2(w01.y, rp, accp[1]);
        accp[2] = ffma2(w23.x, rp, accp[2]);
        accp[3] = ffma2(w23.y, rp, accp[3]);
        off += TT;
    }

    // ---- Phase 2: z_e, normalize, argmin over K=1024 (packed k-pairs) ----
    float e[8];
    upk2(accp[0], e[0], e[1]); upk2(accp[1], e[2], e[3]);
    upk2(accp[2], e[4], e[5]); upk2(accp[3], e[6], e[7]);
    #pragma unroll
    for (int c = 0; c < 8; c++) e[c] = __fadd_rn(e[c], __ldg(in_b + N*8 + c));

    float ssq = 0.f;
    #pragma unroll
    for (int c = 0; c < 8; c++) ssq = __fadd_rn(ssq, __fmul_rn(e[c], e[c]));
    const float rho = fmaxf(__fsqrt_rn(ssq), 1e-12f);
    float en[8];
    #pragma unroll
    for (int c = 0; c < 8; c++) en[c] = __fdiv_rn(e[c], rho);
    float ee = 0.f;
    #pragma unroll
    for (int c = 0; c < 8; c++) ee = __fadd_rn(ee, __fmul_rn(en[c], en[c]));

    unsigned long long en2[8];
    #pragma unroll
    for (int c = 0; c < 8; c++) en2[c] = pk2(en[c], en[c]);
    const unsigned long long eep = pk2(ee, ee);
    const unsigned long long m2  = pk2(-2.f, -2.f);

    float best = 3.4e38f; int bi = 0;
    const unsigned long long* cbu = (const unsigned long long*)cb2_s;
    const unsigned long long* ccu = (const unsigned long long*)cc2_s;
    #pragma unroll 4
    for (int k2 = 0; k2 < KK/2; k2++) {
        const ulonglong2 ca = *(const ulonglong2*)(cbu + k2*8);
        const ulonglong2 cbv = *(const ulonglong2*)(cbu + k2*8 + 2);
        const ulonglong2 cc_ = *(const ulonglong2*)(cbu + k2*8 + 4);
        const ulonglong2 cd = *(const ulonglong2*)(cbu + k2*8 + 6);
        unsigned long long dp = fmul2(en2[0], ca.x);
        dp = ffma2(en2[1], ca.y, dp);
        dp = ffma2(en2[2], cbv.x, dp);
        dp = ffma2(en2[3], cbv.y, dp);
        dp = ffma2(en2[4], cc_.x, dp);
        dp = ffma2(en2[5], cc_.y, dp);
        dp = ffma2(en2[6], cd.x, dp);
        dp = ffma2(en2[7], cd.y, dp);
        // dist = (ee - 2*dot) + cc   (2*dot exact => fma(-2,dot,ee) == ref rounding)
        const unsigned long long tt2 = ffma2(m2, dp, eep);
        const unsigned long long dist2 = fadd2(tt2, ccu[k2]);
        float d0, d1; upk2(dist2, d0, d1);
        if (d0 < best) { best = d0; bi = 2*k2; }
        if (d1 < best) { best = d1; bi = 2*k2 + 1; }
    }

    // ---- Phase 3: winner, straight-through, outputs ----
    const float* qsrc = cb_raw + ((size_t)N*KK + bi)*8;
    const float4 q0 = __ldg((const float4*)qsrc);
    const float4 q1 = __ldg((const float4*)(qsrc + 4));
    const float q[8] = {q0.x, q0.y, q0.z, q0.w, q1.x, q1.y, q1.z, q1.w};

    float lacc = 0.f;
    float zst[8];
    #pragma unroll
    for (int c = 0; c < 8; c++) {
        const float dl = __fsub_rn(e[c], q[c]);
        lacc = fmaf(dl, dl, lacc);
        zst[c] = __fadd_rn(e[c], __fsub_rn(q[c], e[c]));   // z_e + (z_q - z_e)
    }

    out[OFF_CODES + (size_t)b*NCB*TT + (size_t)N*TT + t] = (float)bi;
    #pragma unroll
    for (int c = 0; c < 8; c++)
        out[OFF_LAT + (size_t)b*CN*TT + (size_t)(N*8 + c)*TT + t] = e[c];
    #pragma unroll
    for (int c = 0; c < 8; c++)
        g_zqst[(size_t)c*NT + token] = zst[c];

    red[tid] = lacc; __syncthreads();
    for (int s = 128; s > 0; s >>= 1) {
        if (tid < s) red[tid] += red[tid + s];
        __syncthreads();
    }
    if (tid == 0) g_lpart[N*256 + blockIdx.x] = red[0];
}

// ---------------------------------------------------------------------------
// Final: z_q_out = z - res_9, where res_9 = res_8 - (W_out[8].zqst_8 + ob[8])
// ---------------------------------------------------------------------------
__global__ void __launch_bounds__(256, 2) k_final(const float* __restrict__ z,
                                                  const float* __restrict__ out_b,
                                                  float* __restrict__ out) {
    extern __shared__ float sm[];
    float* wout_s = sm;          // [1024][8] stage 8
    float* ob_s   = sm + 8192;   // [1024]
    const int tid = threadIdx.x;
    const int token = blockIdx.x * 256 + tid;
    const int b = token >> 13;
    const int t = token & (TT - 1);

    for (int i = tid; i < 8192; i += 256) {
        const int d = i >> 3, c = i & 7;
        wout_s[i] = g_Wout[d*CN + 8*8 + c];
    }
    for (int d = tid; d < DD; d += 256) ob_s[d] = out_b[8*DD + d];

    float zq[8];
    #pragma unroll
    for (int c = 0; c < 8; c++) zq[c] = g_zqst[(size_t)c*NT + token];
    __syncthreads();

    size_t off = (size_t)b*DD*TT + t;
    #pragma unroll 4
    for (int d = 0; d < DD; d++) {
        const float r8 = __ldg((const float*)g_res + off);
        float dt = 0.f;
        #pragma unroll
        for (int c = 0; c < 8; c++) dt = fmaf(wout_s[d*8 + c], zq[c], dt);
        const float pr = __fadd_rn(dt, ob_s[d]);
        const float r9 = __fsub_rn(r8, pr);
        out[off] = __fsub_rn(__ldg(z + off), r9);
        off += TT;
    }
}

// ---------------------------------------------------------------------------
// Deterministic loss reduce: cl == cbl (identical forward values)
// ---------------------------------------------------------------------------
__global__ void k_loss(float* __restrict__ out) {
    if (threadIdx.x != 0 || blockIdx.x != 0) return;
    float s = 0.f;
    for (int i = 0; i < NCB*256; i++) s += g_lpart[i];
    const float v = s / 524288.0f;   // per-stage mean over B*C*T, summed over stages
    out[OFF_CL]     = v;
    out[OFF_CL + 1] = v;
}

// ---------------------------------------------------------------------------
extern "C" void kernel_launch(void* const* d_in, const int* in_sizes, int n_in,
                              void* d_out, int out_size) {
    (void)in_sizes; (void)n_in; (void)out_size;
    const float* z     = (const float*)d_in[0];
    const float* in_v  = (const float*)d_in[1];
    const float* in_g  = (const float*)d_in[2];
    const float* in_b  = (const float*)d_in[3];
    const float* out_v = (const float*)d_in[4];
    const float* out_g = (const float*)d_in[5];
    const float* out_b = (const float*)d_in[6];
    const float* cb    = (const float*)d_in[7];
    float* out = (float*)d_out;

    cudaFuncSetAttribute(k_stage<0>, cudaFuncAttributeMaxDynamicSharedMemorySize, SMEM_ST);
    cudaFuncSetAttribute(k_stage<1>, cudaFuncAttributeMaxDynamicSharedMemorySize, SMEM_ST);
    cudaFuncSetAttribute(k_stage<2>, cudaFuncAttributeMaxDynamicSharedMemorySize, SMEM_ST);
    cudaFuncSetAttribute(k_stage<3>, cudaFuncAttributeMaxDynamicSharedMemorySize, SMEM_ST);
    cudaFuncSetAttribute(k_stage<4>, cudaFuncAttributeMaxDynamicSharedMemorySize, SMEM_ST);
    cudaFuncSetAttribute(k_stage<5>, cudaFuncAttributeMaxDynamicSharedMemorySize, SMEM_ST);
    cudaFuncSetAttribute(k_stage<6>, cudaFuncAttributeMaxDynamicSharedMemorySize, SMEM_ST);
    cudaFuncSetAttribute(k_stage<7>, cudaFuncAttributeMaxDynamicSharedMemorySize, SMEM_ST);
    cudaFuncSetAttribute(k_stage<8>, cudaFuncAttributeMaxDynamicSharedMemorySize, SMEM_ST);
    cudaFuncSetAttribute(k_final,    cudaFuncAttributeMaxDynamicSharedMemorySize, SMEM_F);

    kp_win  <<<72, 256>>>(in_v, in_g);
    kp_wout <<<(NCB*DD + 255)/256, 256>>>(out_v, out_g);
    kp_cb   <<<(NCB*KK + 255)/256, 256>>>(cb);

    const int GB = NT / 256;   // 256 blocks
    k_stage<0><<<GB, 256, SMEM_ST>>>(z, in_b, out_b, cb, out);
    k_stage<1><<<GB, 256, SMEM_ST>>>(z, in_b, out_b, cb, out);
    k_stage<2><<<GB, 256, SMEM_ST>>>(z, in_b, out_b, cb, out);
    k_stage<3><<<GB, 256, SMEM_ST>>>(z, in_b, out_b, cb, out);
    k_stage<4><<<GB, 256, SMEM_ST>>>(z, in_b, out_b, cb, out);
    k_stage<5><<<GB, 256, SMEM_ST>>>(z, in_b, out_b, cb, out);
    k_stage<6><<<GB, 256, SMEM_ST>>>(z, in_b, out_b, cb, out);
    k_stage<7><<<GB, 256, SMEM_ST>>>(z, in_b, out_b, cb, out);
    k_stage<8><<<GB, 256, SMEM_ST>>>(z, in_b, out_b, cb, out);
    k_final   <<<GB, 256, SMEM_F>>>(z, out_b, out);
    k_loss    <<<1, 32>>>(out);
}